// round 3
// baseline (speedup 1.0000x reference)
#include <cuda_runtime.h>

#define NIMG 4
#define HW (1024*1024)
#define PBINS 10
#define LBINS 6
#define IBINS 60              // inter bins (l*10+p) in smem
#define NBINS 66              // + 6 label-count bins (60+l) kept in registers
#define TPB 128
#define BLOCKS_PER_IMG 256
#define TOTAL_BLOCKS (BLOCKS_PER_IMG * NIMG)          // 1024
#define VECS_PER_IMG (HW/4)                           // 262144 float4 per image
#define VECS_PER_BLOCK (VECS_PER_IMG/BLOCKS_PER_IMG)  // 1024
#define ITERS (VECS_PER_BLOCK/TPB)                    // 8

// Global scratch (zero-initialized at module load; kernel restores zeros
// before exit so every graph replay sees identical state).
__device__ float g_bins[NIMG][NBINS];
__device__ unsigned int g_ticket;

__global__ void __launch_bounds__(TPB)
sc_fused_kernel(const float* __restrict__ pred,
                const int* __restrict__ pconn,
                const int* __restrict__ lconn,
                float* __restrict__ out) {
    // Per-thread private histogram columns: s[bin][tid].
    // Row stride = 128 floats = 512B (multiple of 128B), so bank = tid%32
    // -> conflict-free regardless of bin value. No atomics in the hot loop.
    // 60 rows * 128 * 4B = 30 KB -> 7 blocks/SM resident.
    __shared__ float s[IBINS][TPB];
    __shared__ float s_part[NBINS][TPB / 32];
    __shared__ bool  s_last;

    const int tid = threadIdx.x;
    const int img = blockIdx.y;

    #pragma unroll
    for (int b = 0; b < IBINS; b++) s[b][tid] = 0.0f;
    __syncthreads();

    const size_t base = (size_t)img * VECS_PER_IMG;
    const float4* __restrict__ p4  = ((const float4*)pred)  + base;
    const int4*   __restrict__ pc4 = ((const int4*)pconn)   + base;
    const int4*   __restrict__ lc4 = ((const int4*)lconn)   + base;

    int v = blockIdx.x * VECS_PER_BLOCK + tid;

    // Label counts: 6 byte-fields packed in a 64-bit register.
    // Max 32 pixels/thread -> each field <= 32, no overflow.
    unsigned long long cnt = 0ULL;

    #pragma unroll 4
    for (int it = 0; it < ITERS; it++, v += TPB) {
        float4 p  = p4[v];
        int4   pc = pc4[v];
        int4   lc = lc4[v];

        s[lc.x * PBINS + pc.x][tid] += p.x;
        s[lc.y * PBINS + pc.y][tid] += p.y;
        s[lc.z * PBINS + pc.z][tid] += p.z;
        s[lc.w * PBINS + pc.w][tid] += p.w;
        cnt += (1ULL << (8 * lc.x)) + (1ULL << (8 * lc.y))
             + (1ULL << (8 * lc.z)) + (1ULL << (8 * lc.w));
    }
    __syncthreads();

    // Reduce 128 private columns per bin: warp shuffle, then 4 partials.
    const int lane = tid & 31;
    const int wid  = tid >> 5;
    #pragma unroll
    for (int b = 0; b < NBINS; b++) {
        float x;
        if (b < IBINS) x = s[b][tid];        // bank = tid%32, conflict-free
        else           x = (float)((cnt >> (8 * (b - IBINS))) & 0xFFULL);
        x += __shfl_down_sync(0xFFFFFFFFu, x, 16);
        x += __shfl_down_sync(0xFFFFFFFFu, x, 8);
        x += __shfl_down_sync(0xFFFFFFFFu, x, 4);
        x += __shfl_down_sync(0xFFFFFFFFu, x, 2);
        x += __shfl_down_sync(0xFFFFFFFFu, x, 1);
        if (lane == 0) s_part[b][wid] = x;
    }
    __syncthreads();

    if (tid < NBINS) {
        float t = s_part[tid][0] + s_part[tid][1] + s_part[tid][2] + s_part[tid][3];
        atomicAdd(&g_bins[img][tid], t);
    }

    // ---- last-block-done: finalize inline, then restore scratch to zero ----
    if (tid == 0) {
        __threadfence();
        unsigned int t = atomicAdd(&g_ticket, 1u);
        s_last = (t == TOTAL_BLOCKS - 1);
    }
    __syncthreads();
    if (!s_last) return;

    // All blocks' atomics visible (threadfence-before-ticket). Read via L2.
    __shared__ float losses[NIMG];
    __shared__ float binc[NIMG][NBINS];

    #pragma unroll
    for (int c = 0; c < 3; c++) {
        int k = tid + c * TPB;
        if (k < NIMG * NBINS)
            ((float*)binc)[k] = __ldcg(&((const float*)g_bins)[k]);
    }
    __syncthreads();

    if (tid < NIMG) {
        const float* b = binc[tid];

        // pred_area[p] = sum_l inter[l][p]
        float pa[PBINS];
        #pragma unroll
        for (int p = 0; p < PBINS; p++) {
            float sum = 0.0f;
            #pragma unroll
            for (int l = 0; l < LBINS; l++) sum += b[l * PBINS + p];
            pa[p] = sum;
        }

        bool colnz[PBINS];
        #pragma unroll
        for (int p = 0; p < PBINS; p++) colnz[p] = false;

        float pair_conn_sum = 0.0f;
        #pragma unroll
        for (int l = 1; l < LBINS; l++) {
            float la = b[IBINS + l];
            float pc = 0.0f;
            int   pn = 0;
            #pragma unroll
            for (int p = 1; p < PBINS; p++) {
                float in = b[l * PBINS + p];
                if (in != 0.0f) {
                    float uni = la + pa[p] - in;
                    pc += in / uni;
                    pn++;
                    colnz[p] = true;
                }
            }
            if (pn > 0) pair_conn_sum += pc / (float)pn;
        }

        int lone = 0;
        #pragma unroll
        for (int p = 1; p < PBINS; p++) if (!colnz[p]) lone++;

        float denom = (float)(LBINS - 1) + (float)lone;
        losses[tid] = 1.0f - pair_conn_sum / denom;
    }
    __syncthreads();

    if (tid == 0)
        out[0] = (losses[0] + losses[1] + losses[2] + losses[3]) * 0.25f;

    // Restore scratch to zero for the next (graph-replayed) call.
    #pragma unroll
    for (int c = 0; c < 3; c++) {
        int k = tid + c * TPB;
        if (k < NIMG * NBINS) ((float*)g_bins)[k] = 0.0f;
    }
    if (tid == 0) g_ticket = 0u;
}

extern "C" void kernel_launch(void* const* d_in, const int* in_sizes, int n_in,
                              void* d_out, int out_size) {
    const float* pred  = (const float*)d_in[0];
    const int*   pconn = (const int*)d_in[1];
    const int*   lconn = (const int*)d_in[2];
    float* out = (float*)d_out;

    dim3 grid(BLOCKS_PER_IMG, NIMG);
    sc_fused_kernel<<<grid, TPB>>>(pred, pconn, lconn, out);
}

// round 4
// speedup vs baseline: 1.0717x; 1.0717x over previous
#include <cuda_runtime.h>

#define NIMG 4
#define HW (1024*1024)
#define PBINS 10
#define LBINS 6
#define IBINS 60              // inter bins (l*10+p) in smem
#define NBINS 66              // + 6 label-count bins (60+l) kept in registers
#define TPB 256
#define NWARPS (TPB/32)
#define BLOCKS_PER_IMG 128
#define TOTAL_BLOCKS (BLOCKS_PER_IMG * NIMG)          // 512
#define VECS_PER_IMG (HW/4)                           // 262144 float4 per image
#define VECS_PER_BLOCK (VECS_PER_IMG/BLOCKS_PER_IMG)  // 2048
#define ITERS (VECS_PER_BLOCK/TPB)                    // 8
#define SMEM_BYTES (IBINS * TPB * 4)                  // 61440 B -> dynamic smem

// Global scratch (zero-initialized at module load; kernel restores zeros
// before exit so every graph replay sees identical state).
__device__ float g_bins[NIMG][NBINS];
__device__ unsigned int g_ticket;

__global__ void __launch_bounds__(TPB)
sc_fused_kernel(const float* __restrict__ pred,
                const int* __restrict__ pconn,
                const int* __restrict__ lconn,
                float* __restrict__ out) {
    // Per-thread private histogram columns: s[bin*TPB + tid].
    // Row stride = 256 floats = 1024B (multiple of 128B), so bank = tid%32
    // -> conflict-free regardless of bin value. No atomics in the hot loop.
    extern __shared__ float s[];             // [IBINS][TPB], 60 KB
    __shared__ float s_part[NBINS][NWARPS];
    __shared__ float losses[NIMG];
    __shared__ float binc[NIMG][NBINS];
    __shared__ bool  s_last;

    const int tid = threadIdx.x;
    const int img = blockIdx.y;

    #pragma unroll
    for (int b = 0; b < IBINS; b++) s[b * TPB + tid] = 0.0f;
    __syncthreads();

    const size_t base = (size_t)img * VECS_PER_IMG;
    const float4* __restrict__ p4  = ((const float4*)pred)  + base;
    const int4*   __restrict__ pc4 = ((const int4*)pconn)   + base;
    const int4*   __restrict__ lc4 = ((const int4*)lconn)   + base;

    int v = blockIdx.x * VECS_PER_BLOCK + tid;

    // Label counts: 6 byte-fields packed in a 64-bit register.
    // Max 32 pixels/thread -> each field <= 32, no overflow.
    unsigned long long cnt = 0ULL;

    #pragma unroll 4
    for (int it = 0; it < ITERS; it++, v += TPB) {
        float4 p  = p4[v];
        int4   pc = pc4[v];
        int4   lc = lc4[v];

        s[(lc.x * PBINS + pc.x) * TPB + tid] += p.x;
        s[(lc.y * PBINS + pc.y) * TPB + tid] += p.y;
        s[(lc.z * PBINS + pc.z) * TPB + tid] += p.z;
        s[(lc.w * PBINS + pc.w) * TPB + tid] += p.w;
        cnt += (1ULL << (8 * lc.x)) + (1ULL << (8 * lc.y))
             + (1ULL << (8 * lc.z)) + (1ULL << (8 * lc.w));
    }
    __syncthreads();

    // Reduce TPB private columns per bin: warp shuffle, then NWARPS partials.
    const int lane = tid & 31;
    const int wid  = tid >> 5;
    #pragma unroll
    for (int b = 0; b < NBINS; b++) {
        float x;
        if (b < IBINS) x = s[b * TPB + tid];   // bank = tid%32, conflict-free
        else           x = (float)((cnt >> (8 * (b - IBINS))) & 0xFFULL);
        x += __shfl_down_sync(0xFFFFFFFFu, x, 16);
        x += __shfl_down_sync(0xFFFFFFFFu, x, 8);
        x += __shfl_down_sync(0xFFFFFFFFu, x, 4);
        x += __shfl_down_sync(0xFFFFFFFFu, x, 2);
        x += __shfl_down_sync(0xFFFFFFFFu, x, 1);
        if (lane == 0) s_part[b][wid] = x;
    }
    __syncthreads();

    if (tid < NBINS) {
        float t = 0.0f;
        #pragma unroll
        for (int w = 0; w < NWARPS; w++) t += s_part[tid][w];
        atomicAdd(&g_bins[img][tid], t);
    }

    // ---- last-block-done: finalize inline, then restore scratch to zero ----
    if (tid == 0) {
        __threadfence();
        unsigned int t = atomicAdd(&g_ticket, 1u);
        s_last = (t == TOTAL_BLOCKS - 1);
    }
    __syncthreads();
    if (!s_last) return;

    // All blocks' atomics visible (threadfence-before-ticket). Read via L2.
    {
        int k = tid;
        #pragma unroll
        for (int c = 0; c < 2; c++, k += TPB)
            if (k < NIMG * NBINS)
                ((float*)binc)[k] = __ldcg(&((const float*)g_bins)[k]);
    }
    __syncthreads();

    if (tid < NIMG) {
        const float* b = binc[tid];

        // pred_area[p] = sum_l inter[l][p]
        float pa[PBINS];
        #pragma unroll
        for (int p = 0; p < PBINS; p++) {
            float sum = 0.0f;
            #pragma unroll
            for (int l = 0; l < LBINS; l++) sum += b[l * PBINS + p];
            pa[p] = sum;
        }

        bool colnz[PBINS];
        #pragma unroll
        for (int p = 0; p < PBINS; p++) colnz[p] = false;

        float pair_conn_sum = 0.0f;
        #pragma unroll
        for (int l = 1; l < LBINS; l++) {
            float la = b[IBINS + l];
            float pc = 0.0f;
            int   pn = 0;
            #pragma unroll
            for (int p = 1; p < PBINS; p++) {
                float in = b[l * PBINS + p];
                if (in != 0.0f) {
                    float uni = la + pa[p] - in;
                    pc += in / uni;
                    pn++;
                    colnz[p] = true;
                }
            }
            if (pn > 0) pair_conn_sum += pc / (float)pn;
        }

        int lone = 0;
        #pragma unroll
        for (int p = 1; p < PBINS; p++) if (!colnz[p]) lone++;

        float denom = (float)(LBINS - 1) + (float)lone;
        losses[tid] = 1.0f - pair_conn_sum / denom;
    }
    __syncthreads();

    if (tid == 0)
        out[0] = (losses[0] + losses[1] + losses[2] + losses[3]) * 0.25f;

    // Restore scratch to zero for the next (graph-replayed) call.
    {
        int k = tid;
        #pragma unroll
        for (int c = 0; c < 2; c++, k += TPB)
            if (k < NIMG * NBINS) ((float*)g_bins)[k] = 0.0f;
    }
    if (tid == 0) g_ticket = 0u;
}

extern "C" void kernel_launch(void* const* d_in, const int* in_sizes, int n_in,
                              void* d_out, int out_size) {
    const float* pred  = (const float*)d_in[0];
    const int*   pconn = (const int*)d_in[1];
    const int*   lconn = (const int*)d_in[2];
    float* out = (float*)d_out;

    // Dynamic smem > 48 KB static cap; attribute set is host-side & idempotent.
    cudaFuncSetAttribute(sc_fused_kernel,
                         cudaFuncAttributeMaxDynamicSharedMemorySize, SMEM_BYTES);

    dim3 grid(BLOCKS_PER_IMG, NIMG);
    sc_fused_kernel<<<grid, TPB, SMEM_BYTES>>>(pred, pconn, lconn, out);
}

// round 5
// speedup vs baseline: 1.4216x; 1.3265x over previous
#include <cuda_runtime.h>

#define NIMG 4
#define HW (1024*1024)
#define PBINS 10
#define LBINS 6
#define IBINS 60              // inter bins (l*10+p) in smem
#define NBINS 66              // + 6 label-count bins (60+l) kept in registers
#define TPB 128
#define NWARPS (TPB/32)
#define BLOCKS_PER_IMG 128
#define TOTAL_BLOCKS (BLOCKS_PER_IMG * NIMG)          // 512
#define VECS_PER_IMG (HW/4)                           // 262144 float4 per image
#define VECS_PER_BLOCK (VECS_PER_IMG/BLOCKS_PER_IMG)  // 2048
#define ITERS (VECS_PER_BLOCK/TPB)                    // 16
#define GROUPS (ITERS/2)                              // 8 double-iter batches

// Global scratch (zero-initialized at module load; kernel restores zeros
// before exit so every graph replay sees identical state).
__device__ float g_bins[NIMG][NBINS];
__device__ unsigned int g_ticket;

__global__ void __launch_bounds__(TPB)
sc_fused_kernel(const float* __restrict__ pred,
                const int* __restrict__ pconn,
                const int* __restrict__ lconn,
                float* __restrict__ out) {
    // Per-thread private histogram columns: s[bin][tid].
    // Row stride = 128 floats = 512B (multiple of 128B), so bank = tid%32
    // -> conflict-free regardless of bin value. No atomics in the hot loop.
    __shared__ float s[IBINS][TPB];                    // 30 KB
    __shared__ float s_part[NBINS][NWARPS];
    __shared__ float losses[NIMG];
    __shared__ float binc[NIMG][NBINS];
    __shared__ bool  s_last;

    const int tid = threadIdx.x;
    const int img = blockIdx.y;

    #pragma unroll
    for (int b = 0; b < IBINS; b++) s[b][tid] = 0.0f;
    __syncthreads();

    const size_t base = (size_t)img * VECS_PER_IMG;
    const float4* __restrict__ p4  = ((const float4*)pred)  + base;
    const int4*   __restrict__ pc4 = ((const int4*)pconn)   + base;
    const int4*   __restrict__ lc4 = ((const int4*)lconn)   + base;

    // Label counts: 6 byte-fields in one 64-bit register (<=64 pixels/thread).
    unsigned long long cnt = 0ULL;

#define PROC(P, C, L)                                                   \
    do {                                                                \
        s[(L).x * PBINS + (C).x][tid] += (P).x;                         \
        s[(L).y * PBINS + (C).y][tid] += (P).y;                         \
        s[(L).z * PBINS + (C).z][tid] += (P).z;                         \
        s[(L).w * PBINS + (C).w][tid] += (P).w;                         \
        cnt += (1ULL << (8 * (L).x)) + (1ULL << (8 * (L).y))            \
             + (1ULL << (8 * (L).z)) + (1ULL << (8 * (L).w));           \
    } while (0)

    // Software pipeline: double-buffered batches of 2 vec-iterations.
    // Batch g+1's 6 LDG.128 issue BEFORE batch g's smem RMW chain, keeping
    // DRAM requests outstanding while the LDS/FADD/STS chain drains.
    int v = blockIdx.x * VECS_PER_BLOCK + tid;

    float4 P0 = __ldcs(&p4[v]);
    int4   C0 = __ldcs(&pc4[v]);
    int4   L0 = __ldcs(&lc4[v]);
    float4 P1 = __ldcs(&p4[v + TPB]);
    int4   C1 = __ldcs(&pc4[v + TPB]);
    int4   L1 = __ldcs(&lc4[v + TPB]);

    int vn = v + 2 * TPB;

    #pragma unroll
    for (int g = 0; g < GROUPS; g++) {
        float4 Q0, Q1; int4 D0, D1, M0, M1;
        if (g < GROUPS - 1) {
            Q0 = __ldcs(&p4[vn]);
            D0 = __ldcs(&pc4[vn]);
            M0 = __ldcs(&lc4[vn]);
            Q1 = __ldcs(&p4[vn + TPB]);
            D1 = __ldcs(&pc4[vn + TPB]);
            M1 = __ldcs(&lc4[vn + TPB]);
        }
        PROC(P0, C0, L0);
        PROC(P1, C1, L1);
        P0 = Q0; C0 = D0; L0 = M0;
        P1 = Q1; C1 = D1; L1 = M1;
        vn += 2 * TPB;
    }
#undef PROC
    __syncthreads();

    // Reduce 128 private columns per bin: warp shuffle, then 4 partials.
    const int lane = tid & 31;
    const int wid  = tid >> 5;
    #pragma unroll
    for (int b = 0; b < NBINS; b++) {
        float x;
        if (b < IBINS) x = s[b][tid];        // bank = tid%32, conflict-free
        else           x = (float)((cnt >> (8 * (b - IBINS))) & 0xFFULL);
        x += __shfl_down_sync(0xFFFFFFFFu, x, 16);
        x += __shfl_down_sync(0xFFFFFFFFu, x, 8);
        x += __shfl_down_sync(0xFFFFFFFFu, x, 4);
        x += __shfl_down_sync(0xFFFFFFFFu, x, 2);
        x += __shfl_down_sync(0xFFFFFFFFu, x, 1);
        if (lane == 0) s_part[b][wid] = x;
    }
    __syncthreads();

    if (tid < NBINS) {
        float t = 0.0f;
        #pragma unroll
        for (int w = 0; w < NWARPS; w++) t += s_part[tid][w];
        atomicAdd(&g_bins[img][tid], t);
    }

    // ---- last-block-done: finalize inline, then restore scratch to zero ----
    if (tid == 0) {
        __threadfence();
        unsigned int t = atomicAdd(&g_ticket, 1u);
        s_last = (t == TOTAL_BLOCKS - 1);
    }
    __syncthreads();
    if (!s_last) return;

    // All blocks' atomics visible (threadfence-before-ticket). Read via L2.
    #pragma unroll
    for (int c = 0; c < 3; c++) {
        int k = tid + c * TPB;
        if (k < NIMG * NBINS)
            ((float*)binc)[k] = __ldcg(&((const float*)g_bins)[k]);
    }
    __syncthreads();

    if (tid < NIMG) {
        const float* b = binc[tid];

        // pred_area[p] = sum_l inter[l][p]
        float pa[PBINS];
        #pragma unroll
        for (int p = 0; p < PBINS; p++) {
            float sum = 0.0f;
            #pragma unroll
            for (int l = 0; l < LBINS; l++) sum += b[l * PBINS + p];
            pa[p] = sum;
        }

        bool colnz[PBINS];
        #pragma unroll
        for (int p = 0; p < PBINS; p++) colnz[p] = false;

        float pair_conn_sum = 0.0f;
        #pragma unroll
        for (int l = 1; l < LBINS; l++) {
            float la = b[IBINS + l];
            float pc = 0.0f;
            int   pn = 0;
            #pragma unroll
            for (int p = 1; p < PBINS; p++) {
                float in = b[l * PBINS + p];
                if (in != 0.0f) {
                    float uni = la + pa[p] - in;
                    pc += in / uni;
                    pn++;
                    colnz[p] = true;
                }
            }
            if (pn > 0) pair_conn_sum += pc / (float)pn;
        }

        int lone = 0;
        #pragma unroll
        for (int p = 1; p < PBINS; p++) if (!colnz[p]) lone++;

        float denom = (float)(LBINS - 1) + (float)lone;
        losses[tid] = 1.0f - pair_conn_sum / denom;
    }
    __syncthreads();

    if (tid == 0)
        out[0] = (losses[0] + losses[1] + losses[2] + losses[3]) * 0.25f;

    // Restore scratch to zero for the next (graph-replayed) call.
    #pragma unroll
    for (int c = 0; c < 3; c++) {
        int k = tid + c * TPB;
        if (k < NIMG * NBINS) ((float*)g_bins)[k] = 0.0f;
    }
    if (tid == 0) g_ticket = 0u;
}

extern "C" void kernel_launch(void* const* d_in, const int* in_sizes, int n_in,
                              void* d_out, int out_size) {
    const float* pred  = (const float*)d_in[0];
    const int*   pconn = (const int*)d_in[1];
    const int*   lconn = (const int*)d_in[2];
    float* out = (float*)d_out;

    dim3 grid(BLOCKS_PER_IMG, NIMG);
    sc_fused_kernel<<<grid, TPB>>>(pred, pconn, lconn, out);
}